// round 11
// baseline (speedup 1.0000x reference)
#include <cuda_runtime.h>
#include <cuda_fp16.h>
#include <cstdint>

#define N_NODES 8192
#define IN_F 256
#define OUT_F 64
#define ALPHA 0.3f
#define LOG2E 1.4426950408889634f
#define MAXNZ 1024
#define NWHBLK 256   // 32 rows per block

// ---------------- device scratch (no allocations allowed) ----------------
__device__ __half g_Whh[N_NODES * OUT_F];   // Wh fp16 [8192][64], 1 MB (L2-resident)
__device__ float g_src2[N_NODES];           // src * log2e
__device__ float g_dst2[N_NODES];           // dst * log2e
__device__ float g_blockmax[NWHBLK];        // per-block max of dst*log2e

__device__ __forceinline__ float ex2f(float x) {
    float r;
    asm("ex2.approx.f32 %0, %1;" : "=f"(r) : "f"(x));
    return r;
}
__device__ __forceinline__ uint32_t smem_u32(const void* p) {
    uint32_t a;
    asm("{ .reg .u64 t; cvta.to.shared.u64 t, %1; cvt.u32.u64 %0, t; }" : "=r"(a) : "l"(p));
    return a;
}
__device__ __forceinline__ void cp16(uint32_t s, const void* g) {
    asm volatile("cp.async.cg.shared.global [%0], [%1], 16;" :: "r"(s), "l"(g));
}
#define CP_COMMIT() asm volatile("cp.async.commit_group;" ::: "memory")
#define CP_WAIT1()  asm volatile("cp.async.wait_group 1;" ::: "memory")
__device__ __forceinline__ void ldmatrix_x4_trans(uint32_t& r0, uint32_t& r1,
                                                  uint32_t& r2, uint32_t& r3,
                                                  uint32_t addr) {
    asm volatile("ldmatrix.sync.aligned.m8n8.x4.trans.shared.b16 {%0,%1,%2,%3}, [%4];"
                 : "=r"(r0), "=r"(r1), "=r"(r2), "=r"(r3) : "r"(addr));
}
__device__ __forceinline__ void mma_16816(float* c, uint32_t a0, uint32_t a1,
                                          uint32_t a2, uint32_t a3,
                                          uint32_t b0, uint32_t b1) {
    asm volatile(
        "mma.sync.aligned.m16n8k16.row.col.f32.f16.f16.f32 "
        "{%0,%1,%2,%3}, {%4,%5,%6,%7}, {%8,%9}, {%0,%1,%2,%3};"
        : "+f"(c[0]), "+f"(c[1]), "+f"(c[2]), "+f"(c[3])
        : "r"(a0), "r"(a1), "r"(a2), "r"(a3), "r"(b0), "r"(b1));
}

// ---------------------------------------------------------------------------
// Kernel 1: Wh = h @ W (fp16 out), scaled src/dst projections, per-block max.
// EXACT R8 structure (measured ~19us): block = 32 rows x 64 feats, 256 thr,
// thread = 2 rows x 4 feats, k-tiled smem GEMM.
// ---------------------------------------------------------------------------
__global__ __launch_bounds__(256) void wh_kernel(const float* __restrict__ h,
                                                 const float* __restrict__ W,
                                                 const float* __restrict__ a) {
    __shared__ float sh[32][68];    // h tile, padded
    __shared__ float sW[64][64];    // W tile (k-major)
    __shared__ float dtile[32];
    const int tid = threadIdx.x;
    const int tx = tid & 15;        // feat group (4 feats)
    const int ty = tid >> 4;        // row pair (rows 2ty, 2ty+1)
    const int I0 = blockIdx.x * 32;

    float acc0[4] = {}, acc1[4] = {};

    for (int kt = 0; kt < 4; kt++) {
        __syncthreads();
#pragma unroll
        for (int it = 0; it < 2; it++) {       // h tile: 512 float4 slots
            const int s = tid + it * 256;
            const int r = s >> 4, c = (s & 15) << 2;
            *reinterpret_cast<float4*>(&sh[r][c]) = *reinterpret_cast<const float4*>(
                &h[(size_t)(I0 + r) * IN_F + kt * 64 + c]);
        }
#pragma unroll
        for (int it = 0; it < 4; it++) {       // W tile: 1024 float4 slots
            const int s = tid + it * 256;
            const int r = s >> 4, c = (s & 15) << 2;
            *reinterpret_cast<float4*>(&sW[r][c]) = *reinterpret_cast<const float4*>(
                &W[(size_t)(kt * 64 + r) * OUT_F + c]);
        }
        __syncthreads();
#pragma unroll 4
        for (int k = 0; k < 64; k++) {
            const float4 wv = *reinterpret_cast<const float4*>(&sW[k][tx << 2]);
            const float h0 = sh[ty * 2][k], h1 = sh[ty * 2 + 1][k];
            acc0[0] += h0 * wv.x; acc0[1] += h0 * wv.y; acc0[2] += h0 * wv.z; acc0[3] += h0 * wv.w;
            acc1[0] += h1 * wv.x; acc1[1] += h1 * wv.y; acc1[2] += h1 * wv.z; acc1[3] += h1 * wv.w;
        }
    }

    // fp16 Wh stores: 8 B per row per thread, coalesced across tx
    {
        const __half2 r0a = __floats2half2_rn(acc0[0], acc0[1]);
        const __half2 r0b = __floats2half2_rn(acc0[2], acc0[3]);
        const __half2 r1a = __floats2half2_rn(acc1[0], acc1[1]);
        const __half2 r1b = __floats2half2_rn(acc1[2], acc1[3]);
        uint2 s0, s1;
        s0.x = *reinterpret_cast<const uint32_t*>(&r0a);
        s0.y = *reinterpret_cast<const uint32_t*>(&r0b);
        s1.x = *reinterpret_cast<const uint32_t*>(&r1a);
        s1.y = *reinterpret_cast<const uint32_t*>(&r1b);
        *reinterpret_cast<uint2*>(&g_Whh[(size_t)(I0 + ty * 2) * OUT_F + tx * 4]) = s0;
        *reinterpret_cast<uint2*>(&g_Whh[(size_t)(I0 + ty * 2 + 1) * OUT_F + tx * 4]) = s1;
    }

    const float4 as = *reinterpret_cast<const float4*>(&a[tx << 2]);
    const float4 ad = *reinterpret_cast<const float4*>(&a[OUT_F + (tx << 2)]);
    float sp0 = acc0[0] * as.x + acc0[1] * as.y + acc0[2] * as.z + acc0[3] * as.w;
    float dp0 = acc0[0] * ad.x + acc0[1] * ad.y + acc0[2] * ad.z + acc0[3] * ad.w;
    float sp1 = acc1[0] * as.x + acc1[1] * as.y + acc1[2] * as.z + acc1[3] * as.w;
    float dp1 = acc1[0] * ad.x + acc1[1] * ad.y + acc1[2] * ad.z + acc1[3] * ad.w;
#pragma unroll
    for (int o = 1; o < 16; o <<= 1) {
        sp0 += __shfl_xor_sync(0xffffffffu, sp0, o);
        dp0 += __shfl_xor_sync(0xffffffffu, dp0, o);
        sp1 += __shfl_xor_sync(0xffffffffu, sp1, o);
        dp1 += __shfl_xor_sync(0xffffffffu, dp1, o);
    }
    if (tx == 0) {
        g_src2[I0 + ty * 2]     = sp0 * LOG2E;
        g_src2[I0 + ty * 2 + 1] = sp1 * LOG2E;
        g_dst2[I0 + ty * 2]     = dp0 * LOG2E;
        g_dst2[I0 + ty * 2 + 1] = dp1 * LOG2E;
        dtile[ty * 2]     = dp0 * LOG2E;
        dtile[ty * 2 + 1] = dp1 * LOG2E;
    }
    __syncthreads();
    if (tid == 0) {
        float mm = dtile[0];
        for (int q = 1; q < 32; q++) mm = fmaxf(mm, dtile[q]);
        g_blockmax[blockIdx.x] = mm;
    }
}

// ---------------------------------------------------------------------------
// Kernel 2: fused masked attention + aggregation + ELU. One block per row i.
// Phases A/compaction identical to the R8/R10 winner. Then:
//   p-phase: p computed ONCE per nz (fp16 plist, padded to 16), den reduced.
//   HMMA gather: warp-autonomous 16-nz segments; cp.async double-buffered
//   Whh-row tiles; A = Wh^T[f][j] via ldmatrix.x4.trans; B = p broadcast
//   over n; 4 mma accumulate D[64 feats] in registers across segments.
// ---------------------------------------------------------------------------
__global__ __launch_bounds__(256) void attn_kernel(const float* __restrict__ adj,
                                                   float* __restrict__ out) {
    const int i = blockIdx.x;
    const int tid = threadIdx.x;
    const int w = tid >> 5;
    const int lane = tid & 31;

    __shared__ unsigned mask[256];
    __shared__ int wsum[8], wbase[8];
    __shared__ float fred[8];
    __shared__ int cnt_s;
    __shared__ float dmax_s, den_s;
    __shared__ unsigned short jlist[MAXNZ];
    __shared__ __half plist[MAXNZ];
    __shared__ __align__(16) __half sTile[8][2][16 * 72];   // warp x buf x rows
    __shared__ float sacc[8][OUT_F];

    const float4* adj4 = reinterpret_cast<const float4*>(adj + (size_t)i * N_NODES);

    // ---- Phase A: issue all 8 adj loads (MLP=8) ----
    float4 v[8];
#pragma unroll
    for (int k = 0; k < 8; k++) v[k] = __ldg(&adj4[k * 256 + tid]);

    // ---- dmax reduction (overlaps adj load latency) ----
    {
        float m = g_blockmax[tid];
#pragma unroll
        for (int o = 16; o; o >>= 1) m = fmaxf(m, __shfl_xor_sync(0xffffffffu, m, o));
        if (lane == 0) fred[w] = m;
    }
    const float srci = __ldg(&g_src2[i]);

    // ---- ballots -> bitmask ----
#pragma unroll
    for (int k = 0; k < 8; k++) {
        const unsigned b0 = __ballot_sync(0xffffffffu, v[k].x != 0.f);
        const unsigned b1 = __ballot_sync(0xffffffffu, v[k].y != 0.f);
        const unsigned b2 = __ballot_sync(0xffffffffu, v[k].z != 0.f);
        const unsigned b3 = __ballot_sync(0xffffffffu, v[k].w != 0.f);
        if (lane == 0) {
            const int wi = (k * 8 + w) << 2;
            mask[wi + 0] = b0; mask[wi + 1] = b1;
            mask[wi + 2] = b2; mask[wi + 3] = b3;
        }
    }
    __syncthreads();
    if (tid == 0) {
        float mm = fred[0];
        for (int q = 1; q < 8; q++) mm = fmaxf(mm, fred[q]);
        dmax_s = mm;
    }

    // ---- deterministic compaction ----
    const unsigned myword = mask[tid];
    const int c = __popc(myword);
    int incl = c;
#pragma unroll
    for (int o = 1; o < 32; o <<= 1) {
        const int x = __shfl_up_sync(0xffffffffu, incl, o);
        if (lane >= o) incl += x;
    }
    if (lane == 31) wsum[w] = incl;
    __syncthreads();
    if (tid == 0) {
        int run = 0;
        for (int q = 0; q < 8; q++) { wbase[q] = run; run += wsum[q]; }
        cnt_s = run < MAXNZ ? run : MAXNZ;
    }
    __syncthreads();
    {
        const int basej = ((tid >> 5) << 10) + (((tid >> 2) & 7) << 7) + (tid & 3);
        int off = wbase[w] + incl - c;
        unsigned m = myword;
        while (m) {
            const int b = __ffs(m) - 1;
            m &= m - 1;
            if (off < MAXNZ) jlist[off] = (unsigned short)(basej + (b << 2));
            off++;
        }
    }
    __syncthreads();
    const int cnt = cnt_s;
    const int cntp = (cnt + 15) & ~15;       // padded to segment multiple

    // proxy upper bound in log2 domain
    float px2 = srci + dmax_s;
    px2 = fmaxf(px2, ALPHA * px2);

    // ---- p-phase: one p per nz (fp16), pad with zeros; den (fp32) ----
    float den = 0.f;
    for (int idx = tid; idx < cntp; idx += 256) {
        const bool ok = idx < cnt;
        const int j = ok ? jlist[idx] : 0;
        if (!ok) jlist[idx] = 0;
        float e = srci + __ldg(&g_dst2[j]);
        e = fmaxf(e, ALPHA * e);
        const float p = ok ? ex2f(e - px2) : 0.f;
        plist[idx] = __float2half(p);
        den += p;
    }
#pragma unroll
    for (int o = 16; o; o >>= 1) den += __shfl_xor_sync(0xffffffffu, den, o);
    if (lane == 0) fred[w] = den;
    __syncthreads();
    if (tid == 0) {
        float s = 0.f;
        for (int q = 0; q < 8; q++) s += fred[q];
        den_s = s;
    }

    // ---- HMMA gather: warp-autonomous segments of 16 nz ----
    const int nseg = cntp >> 4;
    const uint4* whh4 = reinterpret_cast<const uint4*>(g_Whh);
    const uint32_t myTile = smem_u32(&sTile[w][0][0]);
    const int r = lane >> 1, part = lane & 1;           // gather mapping
    const uint32_t dstOff = (uint32_t)(r * 144 + part * 64);
    // ldmatrix.trans lane address parts (A quadrants f x j)
    const uint32_t jrow = (lane & 7) + ((lane & 16) ? 8 : 0);
    const uint32_t fsel = (lane & 8) ? 8 : 0;
    const uint32_t aOff = jrow * 144 + fsel * 2;

    float accc[4][4] = {};

    int buf = 0;
    if (w < nseg) {     // prime segment w
        const int j = jlist[w * 16 + r];
        const uint4* g0 = whh4 + j * 8 + part * 4;
        const uint32_t d0 = myTile + dstOff;
        cp16(d0, g0); cp16(d0 + 16, g0 + 1); cp16(d0 + 32, g0 + 2); cp16(d0 + 48, g0 + 3);
    }
    CP_COMMIT();

    for (int s = w; s < nseg; s += 8) {
        const int nxt = s + 8;
        if (nxt < nseg) {
            const int j = jlist[nxt * 16 + r];
            const uint4* g0 = whh4 + j * 8 + part * 4;
            const uint32_t d0 = myTile + (buf ^ 1) * 2304 + dstOff;
            cp16(d0, g0); cp16(d0 + 16, g0 + 1); cp16(d0 + 32, g0 + 2); cp16(d0 + 48, g0 + 3);
        }
        CP_COMMIT();
        CP_WAIT1();
        __syncwarp();

        // B fragment: p broadcast over n (n-independent -> any D column valid)
        const uint32_t b0 = *reinterpret_cast<const uint32_t*>(&plist[s * 16 + 2 * (lane & 3)]);
        const uint32_t b1 = *reinterpret_cast<const uint32_t*>(&plist[s * 16 + 8 + 2 * (lane & 3)]);

        const uint32_t tb = myTile + buf * 2304 + aOff;
#pragma unroll
        for (int cch = 0; cch < 4; cch++) {
            uint32_t a0, a1, a2, a3;
            ldmatrix_x4_trans(a0, a1, a2, a3, tb + cch * 32);
            mma_16816(accc[cch], a0, a1, a2, a3, b0, b1);
        }
        buf ^= 1;
    }

    // ---- epilogue: column 0 of D -> per-warp partials -> tree reduce ----
    if ((lane & 3) == 0) {
        const int fr = lane >> 2;           // 0..7
#pragma unroll
        for (int cch = 0; cch < 4; cch++) {
            sacc[w][cch * 16 + fr]     = accc[cch][0];
            sacc[w][cch * 16 + fr + 8] = accc[cch][2];
        }
    }
    __syncthreads();

    if (tid < OUT_F) {
        float s = 0.f;
#pragma unroll
        for (int q = 0; q < 8; q++) s += sacc[q][tid];
        float vv = s / den_s;
        vv = vv > 0.f ? vv : expm1f(vv);    // ELU
        out[(size_t)i * OUT_F + tid] = vv;
    }
}

// ---------------------------------------------------------------------------
// inputs: h [8192,256] f32, adj [8192,8192] f32, W [256,64] f32, a [128,1] f32
// output: [8192,64] f32
// ---------------------------------------------------------------------------
extern "C" void kernel_launch(void* const* d_in, const int* in_sizes, int n_in,
                              void* d_out, int out_size) {
    const float* h   = (const float*)d_in[0];
    const float* adj = (const float*)d_in[1];
    const float* W   = (const float*)d_in[2];
    const float* a   = (const float*)d_in[3];
    float* out = (float*)d_out;

    wh_kernel<<<NWHBLK, 256>>>(h, W, a);
    attn_kernel<<<N_NODES, 256>>>(adj, out);
}

// round 12
// speedup vs baseline: 2.3555x; 2.3555x over previous
#include <cuda_runtime.h>
#include <cuda_fp16.h>
#include <cstdint>

#define N_NODES 8192
#define IN_F 256
#define OUT_F 64
#define ALPHA 0.3f
#define LOG2E 1.4426950408889634f
#define MAXNZ 1024
#define NWHBLK 256   // 32 rows per block

// wh dynamic smem layout (bytes)
#define WOFF_H   0          // [32][264] half = 16896
#define WOFF_WT  16896      // [64][264] half = 33792
#define WOFF_D   50688      // [32][72]  half = 4608
#define WOFF_DT  55296      // 32 float  = 128
#define SMEM_WH  55424

// ---------------- device scratch (no allocations allowed) ----------------
__device__ __half g_Whh[N_NODES * OUT_F];   // Wh fp16 [8192][64], 1 MB (L2-resident)
__device__ float g_src2[N_NODES];           // src * log2e
__device__ float g_dst2[N_NODES];           // dst * log2e
__device__ float g_blockmax[NWHBLK];        // per-block max of dst*log2e

__device__ __forceinline__ float ex2f(float x) {
    float r;
    asm("ex2.approx.f32 %0, %1;" : "=f"(r) : "f"(x));
    return r;
}
__device__ __forceinline__ uint32_t smem_u32(const void* p) {
    uint32_t a;
    asm("{ .reg .u64 t; cvta.to.shared.u64 t, %1; cvt.u32.u64 %0, t; }" : "=r"(a) : "l"(p));
    return a;
}
__device__ __forceinline__ void ldmatrix_x4(uint32_t& r0, uint32_t& r1, uint32_t& r2,
                                            uint32_t& r3, uint32_t addr) {
    asm volatile("ldmatrix.sync.aligned.m8n8.x4.shared.b16 {%0,%1,%2,%3}, [%4];"
                 : "=r"(r0), "=r"(r1), "=r"(r2), "=r"(r3) : "r"(addr));
}
__device__ __forceinline__ void mma_16816(float* c, uint32_t a0, uint32_t a1,
                                          uint32_t a2, uint32_t a3,
                                          uint32_t b0, uint32_t b1) {
    asm volatile(
        "mma.sync.aligned.m16n8k16.row.col.f32.f16.f16.f32 "
        "{%0,%1,%2,%3}, {%4,%5,%6,%7}, {%8,%9}, {%0,%1,%2,%3};"
        : "+f"(c[0]), "+f"(c[1]), "+f"(c[2]), "+f"(c[3])
        : "r"(a0), "r"(a1), "r"(a2), "r"(a3), "r"(b0), "r"(b1));
}

// ---------------------------------------------------------------------------
// Kernel 1: Wh = h @ W on the tensor pipe (HMMA).
// Block = 32 rows, 256 threads, grid 256. Stage h (fp16) and W^T (fp16) once;
// 8 warps = 2 m-tiles x 4 n-tiles; 16 k-steps x (2 ldmatrix + 2 mma)/warp.
// Epilogue: fragments -> smem fp16 -> coalesced Whh stores + projections.
// ---------------------------------------------------------------------------
__global__ __launch_bounds__(256) void wh_kernel(const float* __restrict__ h,
                                                 const float* __restrict__ W,
                                                 const float* __restrict__ a) {
    extern __shared__ char wsm[];
    __half* sH  = reinterpret_cast<__half*>(wsm + WOFF_H);   // [32][264]
    __half* sWt = reinterpret_cast<__half*>(wsm + WOFF_WT);  // [64][264]
    __half* sD  = reinterpret_cast<__half*>(wsm + WOFF_D);   // [32][72]
    float* dtile = reinterpret_cast<float*>(wsm + WOFF_DT);

    const int tid = threadIdx.x;
    const int I0 = blockIdx.x * 32;

    // ---- stage h tile as fp16: 2048 float4 slots ----
#pragma unroll
    for (int it = 0; it < 8; it++) {
        const int idx = tid + it * 256;
        const int r = idx >> 6, c4 = idx & 63;
        const float4 v = __ldg(reinterpret_cast<const float4*>(
                              &h[(size_t)(I0 + r) * IN_F]) + c4);
        const __half2 p0 = __floats2half2_rn(v.x, v.y);
        const __half2 p1 = __floats2half2_rn(v.z, v.w);
        uint2 u;
        u.x = *reinterpret_cast<const uint32_t*>(&p0);
        u.y = *reinterpret_cast<const uint32_t*>(&p1);
        *reinterpret_cast<uint2*>(&sH[r * 264 + c4 * 4]) = u;
    }
    // ---- stage W^T as fp16: read W[k][f] coalesced, transpose-store ----
#pragma unroll
    for (int it = 0; it < 16; it++) {
        const int idx = tid + it * 256;
        const int k = idx >> 4, f4 = (idx & 15) << 2;
        const float4 v = __ldg(reinterpret_cast<const float4*>(
                              &W[(size_t)k * OUT_F]) + (idx & 15));
        sWt[(f4 + 0) * 264 + k] = __float2half(v.x);
        sWt[(f4 + 1) * 264 + k] = __float2half(v.y);
        sWt[(f4 + 2) * 264 + k] = __float2half(v.z);
        sWt[(f4 + 3) * 264 + k] = __float2half(v.w);
    }
    __syncthreads();

    const int w = tid >> 5, lane = tid & 31;
    const int wm = w & 1, wn = w >> 1;       // m-tile (16 rows), n-tile (16 feats)
    const uint32_t hbase = smem_u32(sH), wtbase = smem_u32(sWt);
    const uint32_t aAddr = hbase + ((16 * wm + (lane & 15)) * 264 + (lane >> 4) * 8) * 2;
    const uint32_t bRow = (lane & 7) + ((lane & 16) ? 8 : 0);
    const uint32_t bKoff = (lane & 8) ? 8 : 0;
    const uint32_t bAddr = wtbase + ((16 * wn + bRow) * 264 + bKoff) * 2;

    float acc0[4] = {}, acc1[4] = {};
#pragma unroll
    for (int kk = 0; kk < 16; kk++) {
        uint32_t a0, a1, a2, a3, b0, b1, b2, b3;
        ldmatrix_x4(a0, a1, a2, a3, aAddr + kk * 32);
        ldmatrix_x4(b0, b1, b2, b3, bAddr + kk * 32);
        mma_16816(acc0, a0, a1, a2, a3, b0, b1);
        mma_16816(acc1, a0, a1, a2, a3, b2, b3);
    }

    // ---- fragments -> sD fp16 (rows 16wm+gr / +8, cols 16wn + 2t / +8) ----
    {
        const int gr = lane >> 2, t = lane & 3;
        __half2 v;
        v = __floats2half2_rn(acc0[0], acc0[1]);
        *reinterpret_cast<__half2*>(&sD[(16 * wm + gr) * 72 + 16 * wn + 2 * t]) = v;
        v = __floats2half2_rn(acc0[2], acc0[3]);
        *reinterpret_cast<__half2*>(&sD[(16 * wm + gr + 8) * 72 + 16 * wn + 2 * t]) = v;
        v = __floats2half2_rn(acc1[0], acc1[1]);
        *reinterpret_cast<__half2*>(&sD[(16 * wm + gr) * 72 + 16 * wn + 8 + 2 * t]) = v;
        v = __floats2half2_rn(acc1[2], acc1[3]);
        *reinterpret_cast<__half2*>(&sD[(16 * wm + gr + 8) * 72 + 16 * wn + 8 + 2 * t]) = v;
    }
    __syncthreads();

    // ---- coalesced Whh store: thread = (row, 8-half group) ----
    {
        const int r = tid >> 3, g8 = tid & 7;
        *reinterpret_cast<uint4*>(&g_Whh[(size_t)(I0 + r) * OUT_F + g8 * 8]) =
            *reinterpret_cast<const uint4*>(&sD[r * 72 + g8 * 8]);
    }

    // ---- projections: thread = (row, 8 feats), shuffle-reduce over 8 lanes ----
    {
        const int r = tid >> 3, l8 = tid & 7, f0 = l8 * 8;
        const uint4 u = *reinterpret_cast<const uint4*>(&sD[r * 72 + f0]);
        const __half2* hp = reinterpret_cast<const __half2*>(&u);
        float sp = 0.f, dp = 0.f;
#pragma unroll
        for (int q = 0; q < 4; q++) {
            const float2 f2 = __half22float2(hp[q]);
            sp += f2.x * __ldg(&a[f0 + 2 * q]) + f2.y * __ldg(&a[f0 + 2 * q + 1]);
            dp += f2.x * __ldg(&a[OUT_F + f0 + 2 * q]) + f2.y * __ldg(&a[OUT_F + f0 + 2 * q + 1]);
        }
#pragma unroll
        for (int o = 1; o < 8; o <<= 1) {
            sp += __shfl_xor_sync(0xffffffffu, sp, o);
            dp += __shfl_xor_sync(0xffffffffu, dp, o);
        }
        if (l8 == 0) {
            g_src2[I0 + r] = sp * LOG2E;
            g_dst2[I0 + r] = dp * LOG2E;
            dtile[r] = dp * LOG2E;
        }
    }
    __syncthreads();
    if (tid == 0) {
        float mm = dtile[0];
        for (int q = 1; q < 32; q++) mm = fmaxf(mm, dtile[q]);
        g_blockmax[blockIdx.x] = mm;
    }
}

// ---------------------------------------------------------------------------
// Kernel 2: fused masked attention + aggregation + ELU. One block per row i.
// BYTE-IDENTICAL to the R10 winner (80.5 us): batched adj loads -> ballots ->
// deterministic compaction -> single-pass gather with inline proxy-softmax.
// ---------------------------------------------------------------------------
__global__ __launch_bounds__(256) void attn_kernel(const float* __restrict__ adj,
                                                   float* __restrict__ out) {
    const int i = blockIdx.x;
    const int tid = threadIdx.x;
    const int w = tid >> 5;
    const int lane = tid & 31;

    __shared__ unsigned mask[256];
    __shared__ int wsum[8], wbase[8];
    __shared__ float fred[8];
    __shared__ int cnt_s;
    __shared__ float dmax_s, den_s;
    __shared__ unsigned short jlist[MAXNZ];
    __shared__ float acc_red[32][OUT_F];
    __shared__ float fin[4][OUT_F];

    const float4* adj4 = reinterpret_cast<const float4*>(adj + (size_t)i * N_NODES);

    // ---- Phase A: issue all 8 adj loads (MLP=8) ----
    float4 v[8];
#pragma unroll
    for (int k = 0; k < 8; k++) v[k] = __ldg(&adj4[k * 256 + tid]);

    // ---- dmax reduction (overlaps adj load latency) ----
    {
        float m = g_blockmax[tid];
#pragma unroll
        for (int o = 16; o; o >>= 1) m = fmaxf(m, __shfl_xor_sync(0xffffffffu, m, o));
        if (lane == 0) fred[w] = m;
    }
    const float srci = __ldg(&g_src2[i]);

    // ---- ballots -> bitmask ----
#pragma unroll
    for (int k = 0; k < 8; k++) {
        const unsigned b0 = __ballot_sync(0xffffffffu, v[k].x != 0.f);
        const unsigned b1 = __ballot_sync(0xffffffffu, v[k].y != 0.f);
        const unsigned b2 = __ballot_sync(0xffffffffu, v[k].z != 0.f);
        const unsigned b3 = __ballot_sync(0xffffffffu, v[k].w != 0.f);
        if (lane == 0) {
            const int wi = (k * 8 + w) << 2;
            mask[wi + 0] = b0; mask[wi + 1] = b1;
            mask[wi + 2] = b2; mask[wi + 3] = b3;
        }
    }
    __syncthreads();
    if (tid == 0) {
        float mm = fred[0];
        for (int q = 1; q < 8; q++) mm = fmaxf(mm, fred[q]);
        dmax_s = mm;
    }

    // ---- deterministic compaction: exclusive scan of per-word popcounts ----
    const unsigned myword = mask[tid];
    const int c = __popc(myword);
    int incl = c;
#pragma unroll
    for (int o = 1; o < 32; o <<= 1) {
        const int x = __shfl_up_sync(0xffffffffu, incl, o);
        if (lane >= o) incl += x;
    }
    if (lane == 31) wsum[w] = incl;
    __syncthreads();
    if (tid == 0) {
        int run = 0;
        for (int q = 0; q < 8; q++) { wbase[q] = run; run += wsum[q]; }
        cnt_s = run < MAXNZ ? run : MAXNZ;
    }
    __syncthreads();
    {
        // word tid: k = tid>>5, w' = (tid>>2)&7, comp = tid&3
        const int basej = ((tid >> 5) << 10) + (((tid >> 2) & 7) << 7) + (tid & 3);
        int off = wbase[w] + incl - c;
        unsigned m = myword;
        while (m) {
            const int b = __ffs(m) - 1;
            m &= m - 1;
            if (off < MAXNZ) jlist[off] = (unsigned short)(basej + (b << 2));
            off++;
        }
    }
    __syncthreads();
    const int cnt = cnt_s;

    // proxy upper bound in log2 domain: px2 >= lrelu2(src2 + dst2_j) for all j
    float px2 = srci + dmax_s;
    px2 = fmaxf(px2, ALPHA * px2);

    // ---- Phase C: gather with inline p (fp16 Whh rows, fp32 acc, unroll x2) ----
    const int g = lane >> 3;   // 4 nz-groups per warp
    const int s8 = lane & 7;   // 8 lanes x 8 halves = 64 features
    const uint4* whh4 = reinterpret_cast<const uint4*>(g_Whh);
    float acc[8] = {};
    float den = 0.f;

    for (int base = (w << 2); base < cnt; base += 64) {
        const int idx0 = base + g;
        const int idx1 = base + 32 + g;
        int j0 = 0, j1 = 0;
        bool ok0 = idx0 < cnt, ok1 = idx1 < cnt;
        if (ok0) j0 = jlist[idx0];
        if (ok1) j1 = jlist[idx1];
        const float d0 = __ldg(&g_dst2[j0]);
        const float d1 = __ldg(&g_dst2[j1]);
        const uint4 v0 = __ldg(&whh4[j0 * 8 + s8]);
        const uint4 v1 = __ldg(&whh4[j1 * 8 + s8]);
        float e0 = srci + d0, e1 = srci + d1;
        e0 = fmaxf(e0, ALPHA * e0);
        e1 = fmaxf(e1, ALPHA * e1);
        float p0 = ok0 ? ex2f(e0 - px2) : 0.f;
        float p1 = ok1 ? ex2f(e1 - px2) : 0.f;
        den += p0 + p1;
        const __half2* h0 = reinterpret_cast<const __half2*>(&v0);
        const __half2* h1 = reinterpret_cast<const __half2*>(&v1);
#pragma unroll
        for (int q = 0; q < 4; q++) {
            const float2 f0 = __half22float2(h0[q]);
            const float2 f1 = __half22float2(h1[q]);
            acc[2 * q]     += p0 * f0.x + p1 * f1.x;
            acc[2 * q + 1] += p0 * f0.y + p1 * f1.y;
        }
    }

    // den: all 32 lanes summed = 8x true sum (8 lanes per group) -> /8 later
#pragma unroll
    for (int o = 16; o; o >>= 1) den += __shfl_xor_sync(0xffffffffu, den, o);
    if (lane == 0) fred[w] = den;

    const int part = (w << 2) + g;  // 0..31
#pragma unroll
    for (int q = 0; q < 8; q++) acc_red[part][s8 * 8 + q] = acc[q];
    __syncthreads();
    if (tid == 0) {
        float s = 0.f;
        for (int q = 0; q < 8; q++) s += fred[q];
        den_s = s * 0.125f;
    }

    // tree reduce 32 partials -> 4 -> 1, fixed order (deterministic)
    const int f = tid & 63;
    const int c4 = tid >> 6;  // 0..3
    float sp = 0.f;
#pragma unroll
    for (int q = 0; q < 8; q++) sp += acc_red[c4 * 8 + q][f];
    fin[c4][f] = sp;
    __syncthreads();

    if (tid < OUT_F) {
        float vv = (fin[0][tid] + fin[1][tid] + fin[2][tid] + fin[3][tid]) / den_s;
        vv = vv > 0.f ? vv : expm1f(vv);  // ELU
        out[(size_t)i * OUT_F + tid] = vv;
    }
}

// ---------------------------------------------------------------------------
// inputs: h [8192,256] f32, adj [8192,8192] f32, W [256,64] f32, a [128,1] f32
// output: [8192,64] f32
// ---------------------------------------------------------------------------
extern "C" void kernel_launch(void* const* d_in, const int* in_sizes, int n_in,
                              void* d_out, int out_size) {
    const float* h   = (const float*)d_in[0];
    const float* adj = (const float*)d_in[1];
    const float* W   = (const float*)d_in[2];
    const float* a   = (const float*)d_in[3];
    float* out = (float*)d_out;

    static int attr_done = 0;
    if (!attr_done) {
        cudaFuncSetAttribute(wh_kernel, cudaFuncAttributeMaxDynamicSharedMemorySize,
                             SMEM_WH);
        attr_done = 1;
    }

    wh_kernel<<<NWHBLK, 256, SMEM_WH>>>(h, W, a);
    attn_kernel<<<N_NODES, 256>>>(adj, out);
}

// round 13
// speedup vs baseline: 2.3613x; 1.0025x over previous
#include <cuda_runtime.h>
#include <cuda_fp16.h>
#include <cstdint>

#define N_NODES 8192
#define IN_F 256
#define OUT_F 64
#define ALPHA 0.3f
#define LOG2E 1.4426950408889634f
#define MAXNZ 1024
#define NWHBLK 256   // 32 rows per block

// wh dynamic smem layout (bytes)
#define WOFF_H   0          // [32][264] half = 16896
#define WOFF_WT  16896      // [64][264] half = 33792
#define WOFF_D   50688      // [32][72]  half = 4608
#define WOFF_DT  55296      // 32 float  = 128
#define SMEM_WH  55424

// ---------------- device scratch (no allocations allowed) ----------------
__device__ __half g_Whh[N_NODES * OUT_F];   // Wh fp16 [8192][64], 1 MB (L2-resident)
__device__ float g_src2[N_NODES];           // src * log2e
__device__ float g_dst2[N_NODES];           // dst * log2e
__device__ float g_blockmax[NWHBLK];        // per-block max of dst*log2e

__device__ __forceinline__ float ex2f(float x) {
    float r;
    asm("ex2.approx.f32 %0, %1;" : "=f"(r) : "f"(x));
    return r;
}
__device__ __forceinline__ uint32_t smem_u32(const void* p) {
    uint32_t a;
    asm("{ .reg .u64 t; cvta.to.shared.u64 t, %1; cvt.u32.u64 %0, t; }" : "=r"(a) : "l"(p));
    return a;
}
__device__ __forceinline__ void ldmatrix_x4(uint32_t& r0, uint32_t& r1, uint32_t& r2,
                                            uint32_t& r3, uint32_t addr) {
    asm volatile("ldmatrix.sync.aligned.m8n8.x4.shared.b16 {%0,%1,%2,%3}, [%4];"
                 : "=r"(r0), "=r"(r1), "=r"(r2), "=r"(r3) : "r"(addr));
}
__device__ __forceinline__ void mma_16816(float* c, uint32_t a0, uint32_t a1,
                                          uint32_t a2, uint32_t a3,
                                          uint32_t b0, uint32_t b1) {
    asm volatile(
        "mma.sync.aligned.m16n8k16.row.col.f32.f16.f16.f32 "
        "{%0,%1,%2,%3}, {%4,%5,%6,%7}, {%8,%9}, {%0,%1,%2,%3};"
        : "+f"(c[0]), "+f"(c[1]), "+f"(c[2]), "+f"(c[3])
        : "r"(a0), "r"(a1), "r"(a2), "r"(a3), "r"(b0), "r"(b1));
}

// ---------------------------------------------------------------------------
// Kernel 1: Wh = h @ W on the tensor pipe (HMMA).
// Block = 32 rows, 256 threads, grid 256. Stage h (fp16) and W^T (fp16) once;
// 8 warps = 2 m-tiles x 4 n-tiles; 16 k-steps x (2 ldmatrix + 2 mma)/warp.
// Epilogue: fragments -> smem fp16 -> coalesced Whh stores + projections.
// ---------------------------------------------------------------------------
__global__ __launch_bounds__(256) void wh_kernel(const float* __restrict__ h,
                                                 const float* __restrict__ W,
                                                 const float* __restrict__ a) {
    extern __shared__ char wsm[];
    __half* sH  = reinterpret_cast<__half*>(wsm + WOFF_H);   // [32][264]
    __half* sWt = reinterpret_cast<__half*>(wsm + WOFF_WT);  // [64][264]
    __half* sD  = reinterpret_cast<__half*>(wsm + WOFF_D);   // [32][72]
    float* dtile = reinterpret_cast<float*>(wsm + WOFF_DT);

    const int tid = threadIdx.x;
    const int I0 = blockIdx.x * 32;

    // ---- stage h tile as fp16: 2048 float4 slots ----
#pragma unroll
    for (int it = 0; it < 8; it++) {
        const int idx = tid + it * 256;
        const int r = idx >> 6, c4 = idx & 63;
        const float4 v = __ldg(reinterpret_cast<const float4*>(
                              &h[(size_t)(I0 + r) * IN_F]) + c4);
        const __half2 p0 = __floats2half2_rn(v.x, v.y);
        const __half2 p1 = __floats2half2_rn(v.z, v.w);
        uint2 u;
        u.x = *reinterpret_cast<const uint32_t*>(&p0);
        u.y = *reinterpret_cast<const uint32_t*>(&p1);
        *reinterpret_cast<uint2*>(&sH[r * 264 + c4 * 4]) = u;
    }
    // ---- stage W^T as fp16: read W[k][f] coalesced, transpose-store ----
#pragma unroll
    for (int it = 0; it < 16; it++) {
        const int idx = tid + it * 256;
        const int k = idx >> 4, f4 = (idx & 15) << 2;
        const float4 v = __ldg(reinterpret_cast<const float4*>(
                              &W[(size_t)k * OUT_F]) + (idx & 15));
        sWt[(f4 + 0) * 264 + k] = __float2half(v.x);
        sWt[(f4 + 1) * 264 + k] = __float2half(v.y);
        sWt[(f4 + 2) * 264 + k] = __float2half(v.z);
        sWt[(f4 + 3) * 264 + k] = __float2half(v.w);
    }
    __syncthreads();

    const int w = tid >> 5, lane = tid & 31;
    const int wm = w & 1, wn = w >> 1;       // m-tile (16 rows), n-tile (16 feats)
    const uint32_t hbase = smem_u32(sH), wtbase = smem_u32(sWt);
    const uint32_t aAddr = hbase + ((16 * wm + (lane & 15)) * 264 + (lane >> 4) * 8) * 2;
    const uint32_t bRow = (lane & 7) + ((lane & 16) ? 8 : 0);
    const uint32_t bKoff = (lane & 8) ? 8 : 0;
    const uint32_t bAddr = wtbase + ((16 * wn + bRow) * 264 + bKoff) * 2;

    float acc0[4] = {}, acc1[4] = {};
#pragma unroll
    for (int kk = 0; kk < 16; kk++) {
        uint32_t a0, a1, a2, a3, b0, b1, b2, b3;
        ldmatrix_x4(a0, a1, a2, a3, aAddr + kk * 32);
        ldmatrix_x4(b0, b1, b2, b3, bAddr + kk * 32);
        mma_16816(acc0, a0, a1, a2, a3, b0, b1);
        mma_16816(acc1, a0, a1, a2, a3, b2, b3);
    }

    // ---- fragments -> sD fp16 (rows 16wm+gr / +8, cols 16wn + 2t / +8) ----
    {
        const int gr = lane >> 2, t = lane & 3;
        __half2 v;
        v = __floats2half2_rn(acc0[0], acc0[1]);
        *reinterpret_cast<__half2*>(&sD[(16 * wm + gr) * 72 + 16 * wn + 2 * t]) = v;
        v = __floats2half2_rn(acc0[2], acc0[3]);
        *reinterpret_cast<__half2*>(&sD[(16 * wm + gr + 8) * 72 + 16 * wn + 2 * t]) = v;
        v = __floats2half2_rn(acc1[0], acc1[1]);
        *reinterpret_cast<__half2*>(&sD[(16 * wm + gr) * 72 + 16 * wn + 8 + 2 * t]) = v;
        v = __floats2half2_rn(acc1[2], acc1[3]);
        *reinterpret_cast<__half2*>(&sD[(16 * wm + gr + 8) * 72 + 16 * wn + 8 + 2 * t]) = v;
    }
    __syncthreads();

    // ---- coalesced Whh store: thread = (row, 8-half group) ----
    {
        const int r = tid >> 3, g8 = tid & 7;
        *reinterpret_cast<uint4*>(&g_Whh[(size_t)(I0 + r) * OUT_F + g8 * 8]) =
            *reinterpret_cast<const uint4*>(&sD[r * 72 + g8 * 8]);
    }

    // ---- projections: thread = (row, 8 feats), shuffle-reduce over 8 lanes ----
    {
        const int r = tid >> 3, l8 = tid & 7, f0 = l8 * 8;
        const uint4 u = *reinterpret_cast<const uint4*>(&sD[r * 72 + f0]);
        const __half2* hp = reinterpret_cast<const __half2*>(&u);
        float sp = 0.f, dp = 0.f;
#pragma unroll
        for (int q = 0; q < 4; q++) {
            const float2 f2 = __half22float2(hp[q]);
            sp += f2.x * __ldg(&a[f0 + 2 * q]) + f2.y * __ldg(&a[f0 + 2 * q + 1]);
            dp += f2.x * __ldg(&a[OUT_F + f0 + 2 * q]) + f2.y * __ldg(&a[OUT_F + f0 + 2 * q + 1]);
        }
#pragma unroll
        for (int o = 1; o < 8; o <<= 1) {
            sp += __shfl_xor_sync(0xffffffffu, sp, o);
            dp += __shfl_xor_sync(0xffffffffu, dp, o);
        }
        if (l8 == 0) {
            g_src2[I0 + r] = sp * LOG2E;
            g_dst2[I0 + r] = dp * LOG2E;
            dtile[r] = dp * LOG2E;
        }
    }
    __syncthreads();
    if (tid == 0) {
        float mm = dtile[0];
        for (int q = 1; q < 32; q++) mm = fmaxf(mm, dtile[q]);
        g_blockmax[blockIdx.x] = mm;
    }
}

// ---------------------------------------------------------------------------
// Kernel 2: fused masked attention + aggregation + ELU. One block per row i.
// BYTE-IDENTICAL to the R10 winner (80.5 us): batched adj loads -> ballots ->
// deterministic compaction -> single-pass gather with inline proxy-softmax.
// ---------------------------------------------------------------------------
__global__ __launch_bounds__(256) void attn_kernel(const float* __restrict__ adj,
                                                   float* __restrict__ out) {
    const int i = blockIdx.x;
    const int tid = threadIdx.x;
    const int w = tid >> 5;
    const int lane = tid & 31;

    __shared__ unsigned mask[256];
    __shared__ int wsum[8], wbase[8];
    __shared__ float fred[8];
    __shared__ int cnt_s;
    __shared__ float dmax_s, den_s;
    __shared__ unsigned short jlist[MAXNZ];
    __shared__ float acc_red[32][OUT_F];
    __shared__ float fin[4][OUT_F];

    const float4* adj4 = reinterpret_cast<const float4*>(adj + (size_t)i * N_NODES);

    // ---- Phase A: issue all 8 adj loads (MLP=8) ----
    float4 v[8];
#pragma unroll
    for (int k = 0; k < 8; k++) v[k] = __ldg(&adj4[k * 256 + tid]);

    // ---- dmax reduction (overlaps adj load latency) ----
    {
        float m = g_blockmax[tid];
#pragma unroll
        for (int o = 16; o; o >>= 1) m = fmaxf(m, __shfl_xor_sync(0xffffffffu, m, o));
        if (lane == 0) fred[w] = m;
    }
    const float srci = __ldg(&g_src2[i]);

    // ---- ballots -> bitmask ----
#pragma unroll
    for (int k = 0; k < 8; k++) {
        const unsigned b0 = __ballot_sync(0xffffffffu, v[k].x != 0.f);
        const unsigned b1 = __ballot_sync(0xffffffffu, v[k].y != 0.f);
        const unsigned b2 = __ballot_sync(0xffffffffu, v[k].z != 0.f);
        const unsigned b3 = __ballot_sync(0xffffffffu, v[k].w != 0.f);
        if (lane == 0) {
            const int wi = (k * 8 + w) << 2;
            mask[wi + 0] = b0; mask[wi + 1] = b1;
            mask[wi + 2] = b2; mask[wi + 3] = b3;
        }
    }
    __syncthreads();
    if (tid == 0) {
        float mm = fred[0];
        for (int q = 1; q < 8; q++) mm = fmaxf(mm, fred[q]);
        dmax_s = mm;
    }

    // ---- deterministic compaction: exclusive scan of per-word popcounts ----
    const unsigned myword = mask[tid];
    const int c = __popc(myword);
    int incl = c;
#pragma unroll
    for (int o = 1; o < 32; o <<= 1) {
        const int x = __shfl_up_sync(0xffffffffu, incl, o);
        if (lane >= o) incl += x;
    }
    if (lane == 31) wsum[w] = incl;
    __syncthreads();
    if (tid == 0) {
        int run = 0;
        for (int q = 0; q < 8; q++) { wbase[q] = run; run += wsum[q]; }
        cnt_s = run < MAXNZ ? run : MAXNZ;
    }
    __syncthreads();
    {
        // word tid: k = tid>>5, w' = (tid>>2)&7, comp = tid&3
        const int basej = ((tid >> 5) << 10) + (((tid >> 2) & 7) << 7) + (tid & 3);
        int off = wbase[w] + incl - c;
        unsigned m = myword;
        while (m) {
            const int b = __ffs(m) - 1;
            m &= m - 1;
            if (off < MAXNZ) jlist[off] = (unsigned short)(basej + (b << 2));
            off++;
        }
    }
    __syncthreads();
    const int cnt = cnt_s;

    // proxy upper bound in log2 domain: px2 >= lrelu2(src2 + dst2_j) for all j
    float px2 = srci + dmax_s;
    px2 = fmaxf(px2, ALPHA * px2);

    // ---- Phase C: gather with inline p (fp16 Whh rows, fp32 acc, unroll x2) ----
    const int g = lane >> 3;   // 4 nz-groups per warp
    const int s8 = lane & 7;   // 8 lanes x 8 halves = 64 features
    const uint4* whh4 = reinterpret_cast<const uint4*>(g_Whh);
    float acc[8] = {};
    float den = 0.f;

    for (int base = (w << 2); base < cnt; base += 64) {
        const int idx0 = base + g;
        const int idx1 = base + 32 + g;
        int j0 = 0, j1 = 0;
        bool ok0 = idx0 < cnt, ok1 = idx1 < cnt;
        if (ok0) j0 = jlist[idx0];
        if (ok1) j1 = jlist[idx1];
        const float d0 = __ldg(&g_dst2[j0]);
        const float d1 = __ldg(&g_dst2[j1]);
        const uint4 v0 = __ldg(&whh4[j0 * 8 + s8]);
        const uint4 v1 = __ldg(&whh4[j1 * 8 + s8]);
        float e0 = srci + d0, e1 = srci + d1;
        e0 = fmaxf(e0, ALPHA * e0);
        e1 = fmaxf(e1, ALPHA * e1);
        float p0 = ok0 ? ex2f(e0 - px2) : 0.f;
        float p1 = ok1 ? ex2f(e1 - px2) : 0.f;
        den += p0 + p1;
        const __half2* h0 = reinterpret_cast<const __half2*>(&v0);
        const __half2* h1 = reinterpret_cast<const __half2*>(&v1);
#pragma unroll
        for (int q = 0; q < 4; q++) {
            const float2 f0 = __half22float2(h0[q]);
            const float2 f1 = __half22float2(h1[q]);
            acc[2 * q]     += p0 * f0.x + p1 * f1.x;
            acc[2 * q + 1] += p0 * f0.y + p1 * f1.y;
        }
    }

    // den: all 32 lanes summed = 8x true sum (8 lanes per group) -> /8 later
#pragma unroll
    for (int o = 16; o; o >>= 1) den += __shfl_xor_sync(0xffffffffu, den, o);
    if (lane == 0) fred[w] = den;

    const int part = (w << 2) + g;  // 0..31
#pragma unroll
    for (int q = 0; q < 8; q++) acc_red[part][s8 * 8 + q] = acc[q];
    __syncthreads();
    if (tid == 0) {
        float s = 0.f;
        for (int q = 0; q < 8; q++) s += fred[q];
        den_s = s * 0.125f;
    }

    // tree reduce 32 partials -> 4 -> 1, fixed order (deterministic)
    const int f = tid & 63;
    const int c4 = tid >> 6;  // 0..3
    float sp = 0.f;
#pragma unroll
    for (int q = 0; q < 8; q++) sp += acc_red[c4 * 8 + q][f];
    fin[c4][f] = sp;
    __syncthreads();

    if (tid < OUT_F) {
        float vv = (fin[0][tid] + fin[1][tid] + fin[2][tid] + fin[3][tid]) / den_s;
        vv = vv > 0.f ? vv : expm1f(vv);  // ELU
        out[(size_t)i * OUT_F + tid] = vv;
    }
}

// ---------------------------------------------------------------------------
// inputs: h [8192,256] f32, adj [8192,8192] f32, W [256,64] f32, a [128,1] f32
// output: [8192,64] f32
// ---------------------------------------------------------------------------
extern "C" void kernel_launch(void* const* d_in, const int* in_sizes, int n_in,
                              void* d_out, int out_size) {
    const float* h   = (const float*)d_in[0];
    const float* adj = (const float*)d_in[1];
    const float* W   = (const float*)d_in[2];
    const float* a   = (const float*)d_in[3];
    float* out = (float*)d_out;

    static int attr_done = 0;
    if (!attr_done) {
        cudaFuncSetAttribute(wh_kernel, cudaFuncAttributeMaxDynamicSharedMemorySize,
                             SMEM_WH);
        attr_done = 1;
    }

    wh_kernel<<<NWHBLK, 256, SMEM_WH>>>(h, W, a);
    attn_kernel<<<N_NODES, 256>>>(adj, out);
}